// round 8
// baseline (speedup 1.0000x reference)
#include <cuda_runtime.h>
#include <cuda_bf16.h>
#include <cstddef>

// DilateAttention: B=4, d=256, N=8192, HEAD_DIM=32, h=8, ks=3, dil=2.
// Only kernel slots {1,4,7} of the 3x3 unfold are non-zero (sequence treated
// as an Nx1 image) -> neighbors n-2, n, n+2. Six zero slots contribute
// exp(0) each to the softmax denominator.

#define HD 32
#define TILE 128
#define KCOLS 136          // covers global columns [n0-4, n0+132)
#define HALO 4             // offset of n0 inside the k/v tile

__global__ __launch_bounds__(TILE, 6)
void dilate_attn_kernel(const float* __restrict__ q,
                        const float* __restrict__ k,
                        const float* __restrict__ v,
                        float* __restrict__ out,
                        int N) {
    __shared__ float ks_s[HD][KCOLS];
    __shared__ float vs_s[HD][KCOLS];

    const int n0  = blockIdx.x * TILE;
    const int h   = blockIdx.y;
    const int b   = blockIdx.z;
    const int tid = threadIdx.x;

    const size_t chan_base = ((size_t)b * 256 + (size_t)h * HD) * (size_t)N;
    const float* qb = q + chan_base;
    const float* kb = k + chan_base;
    const float* vb = v + chan_base;

    // ---- Load k and v tiles: 32 rows x 136 cols, via float4 (16B aligned:
    // n0 % 128 == 0, halo of 4, N % 4 == 0). Boundary tiles fall back to
    // per-element guarded loads.
    const int NF4 = KCOLS / 4;                 // 34 float4 per row
    for (int idx = tid; idx < HD * NF4; idx += TILE) {
        const int row = idx / NF4;
        const int c4  = idx - row * NF4;
        const int g   = n0 - HALO + c4 * 4;    // global column of first elem
        const size_t roff = (size_t)row * N;
        float4 kv, vv;
        if (g >= 0 && g + 3 < N) {
            kv = *reinterpret_cast<const float4*>(kb + roff + g);
            vv = *reinterpret_cast<const float4*>(vb + roff + g);
        } else {
            float tk[4], tv[4];
            #pragma unroll
            for (int t = 0; t < 4; t++) {
                const int gg = g + t;
                const bool in = (gg >= 0) && (gg < N);
                tk[t] = in ? kb[roff + gg] : 0.0f;
                tv[t] = in ? vb[roff + gg] : 0.0f;
            }
            kv = make_float4(tk[0], tk[1], tk[2], tk[3]);
            vv = make_float4(tv[0], tv[1], tv[2], tv[3]);
        }
        *reinterpret_cast<float4*>(&ks_s[row][c4 * 4]) = kv;
        *reinterpret_cast<float4*>(&vs_s[row][c4 * 4]) = vv;
    }
    __syncthreads();

    // ---- Each thread owns one position n = n0 + tid.
    const int j  = tid;
    const int jc = j + HALO;                   // center column inside tile

    // Three dot products over the 32 channels. q is loaded straight from
    // global: used exactly once, lanes are contiguous -> coalesced, and the
    // fully unrolled loop gives 32 independent in-flight LDGs.
    float s0 = 0.f, s1 = 0.f, s2 = 0.f;
    #pragma unroll
    for (int c = 0; c < HD; c++) {
        const float qv = __ldg(qb + (size_t)c * N + n0 + j);
        s0 = fmaf(qv, ks_s[c][jc - 2], s0);
        s1 = fmaf(qv, ks_s[c][jc],     s1);
        s2 = fmaf(qv, ks_s[c][jc + 2], s2);
    }

    const float scale = 0.17677669529663687f;  // 32^-0.5
    s0 *= scale; s1 *= scale; s2 *= scale;

    // Softmax over 9 slots: six zero logits + {s0,s1,s2}.
    const float m  = fmaxf(0.0f, fmaxf(s0, fmaxf(s1, s2)));
    const float e0 = __expf(s0 - m);
    const float e1 = __expf(s1 - m);
    const float e2 = __expf(s2 - m);
    const float denom = 6.0f * __expf(-m) + e0 + e1 + e2;
    const float inv = 1.0f / denom;
    const float p0 = e0 * inv, p1 = e1 * inv, p2 = e2 * inv;

    // Weighted sum of the three v neighbors, per channel.
    float acc[HD];
    #pragma unroll
    for (int c = 0; c < HD; c++) {
        acc[c] = p0 * vs_s[c][jc - 2] + p1 * vs_s[c][jc] + p2 * vs_s[c][jc + 2];
    }

    // Output layout [B, N, d]: this thread writes 32 contiguous floats
    // (128B, 16B-aligned) -> 8 streaming STG.128 (no L2 allocate: the output
    // is never re-read, keep L2 for the k/v halo reuse).
    float* ob = out + ((size_t)b * N + n0 + j) * 256 + (size_t)h * HD;
    #pragma unroll
    for (int c4 = 0; c4 < 8; c4++) {
        __stwt(reinterpret_cast<float4*>(ob + c4 * 4),
               make_float4(acc[c4 * 4], acc[c4 * 4 + 1],
                           acc[c4 * 4 + 2], acc[c4 * 4 + 3]));
    }
}

extern "C" void kernel_launch(void* const* d_in, const int* in_sizes, int n_in,
                              void* d_out, int out_size) {
    const float* q = (const float*)d_in[0];
    const float* k = (const float*)d_in[1];
    const float* v = (const float*)d_in[2];
    float* out = (float*)d_out;

    const int N = 8192;
    const int d = 256;
    const int B = in_sizes[0] / (N * d);       // = 4
    const int h = d / HD;                      // = 8

    dim3 grid(N / TILE, h, B);
    dilate_attn_kernel<<<grid, TILE>>>(q, k, v, out, N);
}

// round 13
// speedup vs baseline: 1.2753x; 1.2753x over previous
#include <cuda_runtime.h>
#include <cuda_bf16.h>
#include <cstddef>

// DilateAttention: B=4, d=256, N=8192, HEAD_DIM=32, h=8, ks=3, dil=2.
// Only unfold slots {1,4,7} are non-zero -> neighbors n-2, n, n+2; the six
// zero slots contribute exp(0) each to the softmax denominator.
//
// R8 redesign: no shared memory. The 3x k/v neighbor reuse is served by L1
// (offsets -2/0/+2 within a warp hit the same 128B lines), so DRAM traffic
// stays ~1x per tensor while removing the 35KB smem occupancy cap, the
// barrier, and the acc[] register array. __launch_bounds__(128,8) caps regs
// at 64 -> 8 CTAs/SM = 50% occupancy (vs 31% measured for the smem version).

#define HD 32

__global__ __launch_bounds__(128, 8)
void dilate_attn_kernel(const float* __restrict__ q,
                        const float* __restrict__ k,
                        const float* __restrict__ v,
                        float* __restrict__ out,
                        int N) {
    const int n   = blockIdx.x * 128 + threadIdx.x;
    const int h   = blockIdx.y;
    const int b   = blockIdx.z;

    const size_t chan_base = ((size_t)b * 256 + (size_t)h * HD) * (size_t)N;
    const float* qb = q + chan_base + n;
    const float* kb = k + chan_base + n;
    const float* vb = v + chan_base + n;

    const bool lo = (n >= 2);        // n-2 in range
    const bool hi = (n + 2 < N);     // n+2 in range

    // ---- Scores: three dot products over 32 channels. 4 independent LDGs
    // per channel, fully unrolled -> deep MLP. All loads coalesced; the +-2
    // offsets hit lines already fetched by neighboring lanes (L1 reuse).
    float s0 = 0.f, s1 = 0.f, s2 = 0.f;
    #pragma unroll
    for (int c = 0; c < HD; c++) {
        const size_t off = (size_t)c * N;
        const float qv = __ldg(qb + off);
        const float k0 = lo ? __ldg(kb + off - 2) : 0.0f;
        const float k1 = __ldg(kb + off);
        const float k2 = hi ? __ldg(kb + off + 2) : 0.0f;
        s0 = fmaf(qv, k0, s0);
        s1 = fmaf(qv, k1, s1);
        s2 = fmaf(qv, k2, s2);
    }

    const float scale = 0.17677669529663687f;  // 32^-0.5
    s0 *= scale; s1 *= scale; s2 *= scale;

    // Softmax over 9 slots: six zero logits + {s0,s1,s2}.
    const float m  = fmaxf(0.0f, fmaxf(s0, fmaxf(s1, s2)));
    const float e0 = __expf(s0 - m);
    const float e1 = __expf(s1 - m);
    const float e2 = __expf(s2 - m);
    const float inv = 1.0f / (6.0f * __expf(-m) + e0 + e1 + e2);
    const float p0 = e0 * inv, p1 = e1 * inv, p2 = e2 * inv;

    // ---- Output: weighted sum of the three v neighbors, streamed in float4
    // chunks (no 32-reg accumulator array). Thread writes its whole 128B
    // line at out[(b*N+n)*256 + h*32] via streaming stores (never re-read).
    float* ob = out + ((size_t)b * N + n) * 256 + (size_t)h * HD;
    #pragma unroll
    for (int c4 = 0; c4 < 8; c4++) {
        float r[4];
        #pragma unroll
        for (int t = 0; t < 4; t++) {
            const size_t off = (size_t)(c4 * 4 + t) * N;
            const float v0 = lo ? __ldg(vb + off - 2) : 0.0f;
            const float v1 = __ldg(vb + off);
            const float v2 = hi ? __ldg(vb + off + 2) : 0.0f;
            r[t] = p0 * v0 + p1 * v1 + p2 * v2;
        }
        __stwt(reinterpret_cast<float4*>(ob + c4 * 4),
               make_float4(r[0], r[1], r[2], r[3]));
    }
}

extern "C" void kernel_launch(void* const* d_in, const int* in_sizes, int n_in,
                              void* d_out, int out_size) {
    const float* q = (const float*)d_in[0];
    const float* k = (const float*)d_in[1];
    const float* v = (const float*)d_in[2];
    float* out = (float*)d_out;

    const int N = 8192;
    const int d = 256;
    const int B = in_sizes[0] / (N * d);       // = 4
    const int h = d / HD;                      // = 8

    dim3 grid(N / 128, h, B);
    dilate_attn_kernel<<<grid, 128>>>(q, k, v, out, N);
}